// round 15
// baseline (speedup 1.0000x reference)
#include <cuda_runtime.h>
#include <cuda_fp16.h>
#include <cstdint>
#include <math.h>

#define D_MODEL 1024
#define D_VOCAB 32000
#define NB 4
#define SEQ 1024
#define BT (NB * SEQ)
#define NLAYERS 6
#define BTV ((long)BT * D_VOCAB)
#define D2 (2 * D_MODEL)
#define LSE_NB (D_VOCAB / 128)     // 250 column blocks in the logits GEMM

// ---------------- scratch (device globals) ----------------------------------
__device__ float g_z [BT * D_MODEL];
__device__ float g_nll[BT];
__device__ float2 g_lse[(long)BT * LSE_NB];

__device__ __half g_ylnf[BT * D_MODEL];
__device__ __half g_qkf [BT * D2];
__device__ __half g_s16 [NB * SEQ * SEQ];     // raw scores, fp16
__device__ __half g_sf  [NB * SEQ * SEQ];     // softmaxed, fp16
__device__ __half g_o16 [BT * D_MODEL];       // attention output, fp16
__device__ __half g_vTf [BT * D_MODEL];
__device__ __half g_hf  [BT * D_MODEL];
__device__ __half g_zf  [BT * D_MODEL];
__device__ __half g_encf[(long)D_VOCAB * D_MODEL];
__device__ __half g_wtf [5 * D_MODEL * D_MODEL];   // wqT wkT wvT w1T w2T

// ---------------- helpers ----------------------------------------------------
__device__ __forceinline__ uint32_t smem_u32(const void* p) {
    uint32_t a;
    asm("{ .reg .u64 t; cvta.to.shared.u64 t, %1; cvt.u32.u64 %0, t; }" : "=r"(a) : "l"(p));
    return a;
}
__device__ __forceinline__ void ldsm4(uint32_t addr, uint32_t& r0, uint32_t& r1,
                                      uint32_t& r2, uint32_t& r3) {
    asm volatile("ldmatrix.sync.aligned.m8n8.x4.shared.b16 {%0,%1,%2,%3}, [%4];"
                 : "=r"(r0), "=r"(r1), "=r"(r2), "=r"(r3) : "r"(addr));
}
__device__ __forceinline__ void mma_fp16(float* c, uint32_t a0, uint32_t a1,
                                         uint32_t a2, uint32_t a3,
                                         uint32_t b0, uint32_t b1) {
    asm volatile(
        "mma.sync.aligned.m16n8k16.row.col.f32.f16.f16.f32 "
        "{%0,%1,%2,%3}, {%4,%5,%6,%7}, {%8,%9}, {%0,%1,%2,%3};"
        : "+f"(c[0]), "+f"(c[1]), "+f"(c[2]), "+f"(c[3])
        : "r"(a0), "r"(a1), "r"(a2), "r"(a3), "r"(b0), "r"(b1));
}
#define CP16(dst, src) \
    asm volatile("cp.async.cg.shared.global [%0], [%1], 16;" :: "r"(dst), "l"(src))
#define CP_COMMIT() asm volatile("cp.async.commit_group;" ::: "memory")
#define CP_WAIT1()  asm volatile("cp.async.wait_group 1;" ::: "memory")

// warp reduce; op 0 = sum, 1 = max
template <int OP>
__device__ __forceinline__ float warp_red(float v) {
    #pragma unroll
    for (int o = 16; o; o >>= 1) {
        float t = __shfl_xor_sync(0xffffffffu, v, o);
        v = OP ? fmaxf(v, t) : v + t;
    }
    return v;
}
__device__ __forceinline__ void h2f(uint32_t u, float& a, float& b) {
    __half2 h = *(__half2*)&u;
    float2 f = __half22float2(h);
    a = f.x; b = f.y;
}

// ---------------- fp16 single-pass GEMM NT (K-tile 32, NSTAGE 3) -------------
// flags: 1=relu 2=accum-C-fp32 4=bias 8=fp16-out(Cf) 16=fp32-out(C)
//        32=emit per-(row, colblock) logsumexp partials into g_lse
#define H_STAGE 16384
#define NSTAGE 3
__global__ __launch_bounds__(256, 2) void gemm_h(
    const __half* __restrict__ A, const __half* __restrict__ B,
    const float* __restrict__ bias, float* __restrict__ C,
    __half* __restrict__ Cf,
    int lda, int ldb, int ldc, long sA, long sB, long sC,
    int K, float alpha, int flags) {

    extern __shared__ __align__(16) uint8_t sm[];

    A += (long)blockIdx.z * sA;
    B += (long)blockIdx.z * sB;
    if (C)  C  += (long)blockIdx.z * sC;
    if (Cf) Cf += (long)blockIdx.z * sC;

    const int tid  = threadIdx.x;
    const int wid  = tid >> 5;
    const int lane = tid & 31;
    const int warp_m = wid & 3;
    const int warp_n = wid >> 2;
    const int row0 = blockIdx.x * 128;
    const int col0 = blockIdx.y * 128;

    const uint32_t sbase = smem_u32(sm);

    const int lr = tid >> 1;
    const int lq = tid & 1;
    const int swz = (lr >> 1) & 3;
    const __half* Ap = A + (long)(row0 + lr) * lda;
    const __half* Bp = B + (long)(col0 + lr) * ldb;

    float acc[2][8][4];
    #pragma unroll
    for (int mb = 0; mb < 2; mb++)
        #pragma unroll
        for (int nb = 0; nb < 8; nb++)
            #pragma unroll
            for (int i = 0; i < 4; i++) acc[mb][nb][i] = 0.f;

    auto load_tile = [&](int kt, int st) {
        int k0 = kt << 5;
        uint32_t sb = sbase + st * H_STAGE;
        #pragma unroll
        for (int j = 0; j < 2; j++) {
            int c = lq * 2 + j;
            uint32_t off = (uint32_t)(lr * 64 + (c ^ swz) * 16);
            CP16(sb + off,        Ap + k0 + c * 8);
            CP16(sb + 8192 + off, Bp + k0 + c * 8);
        }
    };

    const int KT = K >> 5;
    load_tile(0, 0); CP_COMMIT();
    if (KT > 1) { load_tile(1, 1); CP_COMMIT(); }
    else        { CP_COMMIT(); }

    for (int kt = 0; kt < KT; kt++) {
        CP_WAIT1();
        __syncthreads();
        if (kt + 2 < KT) load_tile(kt + 2, (kt + 2) % NSTAGE);
        CP_COMMIT();

        uint32_t sb = sbase + (kt % NSTAGE) * H_STAGE;
        #pragma unroll
        for (int kc = 0; kc < 2; kc++) {
            const int chunkA = kc * 2 + (lane >> 4);
            uint32_t ah[2][4];
            #pragma unroll
            for (int mb = 0; mb < 2; mb++) {
                int mrow = warp_m * 32 + mb * 16 + (lane & 15);
                uint32_t off = (uint32_t)(mrow * 64 + (chunkA ^ ((mrow >> 1) & 3)) * 16);
                ldsm4(sb + off, ah[mb][0], ah[mb][1], ah[mb][2], ah[mb][3]);
            }
            #pragma unroll
            for (int nb4 = 0; nb4 < 4; nb4++) {
                int nrow = warp_n * 64 + nb4 * 16 + (lane & 15);
                uint32_t off = (uint32_t)(nrow * 64 + (chunkA ^ ((nrow >> 1) & 3)) * 16);
                uint32_t b0, b1, b2, b3;
                ldsm4(sb + 8192 + off, b0, b1, b2, b3);
                #pragma unroll
                for (int mb = 0; mb < 2; mb++) {
                    mma_fp16(acc[mb][nb4 * 2],     ah[mb][0], ah[mb][1], ah[mb][2], ah[mb][3], b0, b2);
                    mma_fp16(acc[mb][nb4 * 2 + 1], ah[mb][0], ah[mb][1], ah[mb][2], ah[mb][3], b1, b3);
                }
            }
        }
    }

    // ---- standard epilogue ----
    #pragma unroll
    for (int mb = 0; mb < 2; mb++) {
        #pragma unroll
        for (int nb = 0; nb < 8; nb++) {
            int m0 = row0 + warp_m * 32 + mb * 16 + (lane >> 2);
            int n0 = col0 + warp_n * 64 + nb * 8 + (lane & 3) * 2;
            #pragma unroll
            for (int half = 0; half < 2; half++) {
                int m = m0 + half * 8;
                float v0 = acc[mb][nb][half * 2 + 0] * alpha;
                float v1 = acc[mb][nb][half * 2 + 1] * alpha;
                if (flags & 4) { v0 += bias[n0]; v1 += bias[n0 + 1]; }
                if (flags & 1) { v0 = fmaxf(v0, 0.f); v1 = fmaxf(v1, 0.f); }
                long idx = (long)m * ldc + n0;
                if (flags & 2) { float2 o = *(float2*)(C + idx); v0 += o.x; v1 += o.y; }
                if (flags & 16) *(float2*)(C + idx) = make_float2(v0, v1);
                if (flags & 8)  *(__half2*)(Cf + idx) = __floats2half2_rn(v0, v1);
            }
        }
    }

    // ---- fused logsumexp partials (logits GEMM only; alpha == 1) ----
    if (flags & 32) {
        __shared__ float2 lse_sh[128];
        float msm[2][2], mss[2][2];
        #pragma unroll
        for (int mb = 0; mb < 2; mb++) {
            #pragma unroll
            for (int half = 0; half < 2; half++) {
                float lm = -1e30f;
                #pragma unroll
                for (int nb = 0; nb < 8; nb++)
                    lm = fmaxf(lm, fmaxf(acc[mb][nb][half * 2], acc[mb][nb][half * 2 + 1]));
                float ls = 0.f;
                #pragma unroll
                for (int nb = 0; nb < 8; nb++)
                    ls += expf(acc[mb][nb][half * 2] - lm) +
                          expf(acc[mb][nb][half * 2 + 1] - lm);
                #pragma unroll
                for (int o = 1; o <= 2; o <<= 1) {
                    float m2 = __shfl_xor_sync(0xffffffffu, lm, o);
                    float s2 = __shfl_xor_sync(0xffffffffu, ls, o);
                    float M = fmaxf(lm, m2);
                    ls = ls * expf(lm - M) + s2 * expf(m2 - M);
                    lm = M;
                }
                msm[mb][half] = lm; mss[mb][half] = ls;
                int lrow = warp_m * 32 + mb * 16 + half * 8 + (lane >> 2);
                if (warp_n == 1 && (lane & 3) == 0)
                    lse_sh[lrow] = make_float2(lm, ls);
            }
        }
        __syncthreads();
        if (warp_n == 0 && (lane & 3) == 0) {
            float2* lse = g_lse;
            #pragma unroll
            for (int mb = 0; mb < 2; mb++) {
                #pragma unroll
                for (int half = 0; half < 2; half++) {
                    int lrow = warp_m * 32 + mb * 16 + half * 8 + (lane >> 2);
                    float2 o = lse_sh[lrow];
                    float M = fmaxf(msm[mb][half], o.x);
                    float S = mss[mb][half] * expf(msm[mb][half] - M) +
                              o.y * expf(o.x - M);
                    lse[(long)(row0 + lrow) * gridDim.y + blockIdx.y] = make_float2(M, S);
                }
            }
        }
    }
}

// ---------------- transpose + fp32->fp16 -------------------------------------
__global__ void transpose_half(const float* __restrict__ src, __half* __restrict__ dst,
                               int R, int Ccols) {
    __shared__ float t[32][33];
    long ofs = (long)blockIdx.z * R * Ccols;
    src += ofs; dst += ofs;
    int bx = blockIdx.x * 32, by = blockIdx.y * 32;
    int x = bx + threadIdx.x;
    #pragma unroll
    for (int j = 0; j < 32; j += 8) {
        int y = by + threadIdx.y + j;
        t[threadIdx.y + j][threadIdx.x] = src[(long)y * Ccols + x];
    }
    __syncthreads();
    x = by + threadIdx.x;
    #pragma unroll
    for (int j = 0; j < 32; j += 8) {
        int y = bx + threadIdx.y + j;
        dst[(long)y * R + x] = __float2half_rn(t[threadIdx.x][threadIdx.y + j]);
    }
}

// ---------------- fp32 -> fp16 convert ---------------------------------------
__global__ void tohalf_kernel(const float* __restrict__ src, __half* __restrict__ dst,
                              long n4) {
    long i = (long)blockIdx.x * blockDim.x + threadIdx.x;
    long stride = (long)gridDim.x * blockDim.x;
    for (; i < n4; i += stride) {
        float4 v = ((const float4*)src)[i];
        ((__half2*)dst)[i * 2]     = __floats2half2_rn(v.x, v.y);
        ((__half2*)dst)[i * 2 + 1] = __floats2half2_rn(v.z, v.w);
    }
}

// ---------------- embedding gather ------------------------------------------
__global__ void embed_kernel(const int* __restrict__ x, const float* __restrict__ enc,
                             float* __restrict__ z) {
    int row = blockIdx.x;
    int tok = x[row];
    const float4* src = (const float4*)(enc + (long)tok * D_MODEL);
    float4* dst = (float4*)(z + (long)row * D_MODEL);
    for (int i = threadIdx.x; i < D_MODEL / 4; i += blockDim.x) dst[i] = src[i];
}

// ---------------- (buggy) LayerNorm, warp-per-row, fp32 input ----------------
__global__ __launch_bounds__(256) void ln_kernel(
    const float* __restrict__ in, const float* __restrict__ gamma,
    const float* __restrict__ beta, __half* __restrict__ outf) {
    int row  = blockIdx.x * 8 + (threadIdx.x >> 5);
    int lane = threadIdx.x & 31;
    const float4* xr = (const float4*)(in + (long)row * D_MODEL);

    float4 xv[8];
    float s = 0.f, s2 = 0.f;
    #pragma unroll
    for (int j = 0; j < 8; j++) {
        xv[j] = xr[lane + 32 * j];
        s  += xv[j].x + xv[j].y + xv[j].z + xv[j].w;
        s2 += xv[j].x * xv[j].x + xv[j].y * xv[j].y
            + xv[j].z * xv[j].z + xv[j].w * xv[j].w;
    }
    float S  = warp_red<0>(s);
    float S2 = warp_red<0>(s2);
    float mu  = S * (1.f / (float)D_MODEL);
    float var = (S2 - (float)D_MODEL * mu * mu) * (1.f / (float)(D_MODEL - 1));
    float shift = mu * rsqrtf(var);

    #pragma unroll
    for (int j = 0; j < 8; j++) {
        float4 g = ((const float4*)gamma)[lane + 32 * j];
        float4 b = ((const float4*)beta)[lane + 32 * j];
        long base = (long)row * D_MODEL + (lane + 32 * j) * 4;
        *(__half2*)(outf + base)     = __floats2half2_rn((xv[j].x - shift) * g.x + b.x,
                                                         (xv[j].y - shift) * g.y + b.y);
        *(__half2*)(outf + base + 2) = __floats2half2_rn((xv[j].z - shift) * g.z + b.z,
                                                         (xv[j].w - shift) * g.w + b.w);
    }
}

// ---------------- (buggy) LayerNorm, warp-per-row, fp16 input ----------------
__global__ __launch_bounds__(256) void ln_h_kernel(
    const __half* __restrict__ in, const float* __restrict__ gamma,
    const float* __restrict__ beta, __half* __restrict__ outf) {
    int row  = blockIdx.x * 8 + (threadIdx.x >> 5);
    int lane = threadIdx.x & 31;
    const uint4* xr = (const uint4*)(in + (long)row * D_MODEL);  // 8 halves per uint4

    float f[32];
    float s = 0.f, s2 = 0.f;
    #pragma unroll
    for (int j = 0; j < 4; j++) {
        uint4 r = xr[lane + 32 * j];
        h2f(r.x, f[j*8+0], f[j*8+1]); h2f(r.y, f[j*8+2], f[j*8+3]);
        h2f(r.z, f[j*8+4], f[j*8+5]); h2f(r.w, f[j*8+6], f[j*8+7]);
        #pragma unroll
        for (int k = 0; k < 8; k++) { s += f[j*8+k]; s2 += f[j*8+k] * f[j*8+k]; }
    }
    float S  = warp_red<0>(s);
    float S2 = warp_red<0>(s2);
    float mu  = S * (1.f / (float)D_MODEL);
    float var = (S2 - (float)D_MODEL * mu * mu) * (1.f / (float)(D_MODEL - 1));
    float shift = mu * rsqrtf(var);

    #pragma unroll
    for (int j = 0; j < 4; j++) {
        long base = (long)row * D_MODEL + (lane + 32 * j) * 8;
        #pragma unroll
        for (int t = 0; t < 2; t++) {
            float4 g = ((const float4*)gamma)[(lane + 32 * j) * 2 + t];
            float4 b = ((const float4*)beta)[(lane + 32 * j) * 2 + t];
            int o = j * 8 + t * 4;
            *(__half2*)(outf + base + t * 4)     = __floats2half2_rn((f[o+0] - shift) * g.x + b.x,
                                                                     (f[o+1] - shift) * g.y + b.y);
            *(__half2*)(outf + base + t * 4 + 2) = __floats2half2_rn((f[o+2] - shift) * g.z + b.z,
                                                                     (f[o+3] - shift) * g.w + b.w);
        }
    }
}

// ---------------- softmax, warp-per-row, fp16 input -> fp16 ------------------
__global__ __launch_bounds__(256) void softmax_kernel(
    const __half* __restrict__ s, __half* __restrict__ outf) {
    int row  = blockIdx.x * 8 + (threadIdx.x >> 5);
    int lane = threadIdx.x & 31;
    const uint4* r4 = (const uint4*)(s + (long)row * SEQ);

    float f[32];
    float m = -1e30f;
    #pragma unroll
    for (int j = 0; j < 4; j++) {
        uint4 r = r4[lane + 32 * j];
        h2f(r.x, f[j*8+0], f[j*8+1]); h2f(r.y, f[j*8+2], f[j*8+3]);
        h2f(r.z, f[j*8+4], f[j*8+5]); h2f(r.w, f[j*8+6], f[j*8+7]);
        #pragma unroll
        for (int k = 0; k < 8; k++) m = fmaxf(m, f[j*8+k]);
    }
    float mx = warp_red<1>(m);

    float sum = 0.f;
    #pragma unroll
    for (int j = 0; j < 32; j++) { f[j] = expf(f[j] - mx); sum += f[j]; }
    float inv = 1.f / warp_red<0>(sum);

    #pragma unroll
    for (int j = 0; j < 4; j++) {
        long base = (long)row * SEQ + (lane + 32 * j) * 8;
        #pragma unroll
        for (int t = 0; t < 4; t++)
            *(__half2*)(outf + base + t * 2) =
                __floats2half2_rn(f[j*8 + t*2] * inv, f[j*8 + t*2 + 1] * inv);
    }
}

// ---------------- final NLL from per-colblock LSE partials -------------------
__global__ void nll_final(const float2* __restrict__ lse,
                          const float* __restrict__ logits,
                          const int* __restrict__ y, float* __restrict__ nll) {
    int row = blockIdx.x;
    int tid = threadIdx.x;

    float m = -1e30f, s = 0.f;
    if (tid < LSE_NB) {
        float2 p = lse[(long)row * LSE_NB + tid];
        m = p.x; s = p.y;
    }

    int lane = tid & 31, wid = tid >> 5;
    #pragma unroll
    for (int o = 16; o; o >>= 1) {
        float m2 = __shfl_xor_sync(0xffffffffu, m, o);
        float s2 = __shfl_xor_sync(0xffffffffu, s, o);
        float M = fmaxf(m, m2);
        s = s * expf(m - M) + s2 * expf(m2 - M);
        m = M;
    }
    __shared__ float sm_[8], ss_[8];
    if (lane == 0) { sm_[wid] = m; ss_[wid] = s; }
    __syncthreads();
    if (tid == 0) {
        float M = sm_[0];
        #pragma unroll
        for (int i = 1; i < 8; i++) M = fmaxf(M, sm_[i]);
        float S = 0.f;
        #pragma unroll
        for (int i = 0; i < 8; i++) S += ss_[i] * expf(sm_[i] - M);
        nll[row] = (M + logf(S)) - logits[(long)row * D_VOCAB + y[row]];
    }
}

__global__ void loss_reduce_kernel(const float* __restrict__ nll, float* __restrict__ out,
                                   long ofs) {
    __shared__ float red[256];
    int tid = threadIdx.x;
    float s = 0.f;
    for (int i = tid; i < BT; i += 256) s += nll[i];
    red[tid] = s; __syncthreads();
    #pragma unroll
    for (int o = 128; o > 0; o >>= 1) { if (tid < o) red[tid] += red[tid + o]; __syncthreads(); }
    if (tid == 0) out[ofs] = red[0] / (float)BT;
}

// ---------------- driver -----------------------------------------------------
extern "C" void kernel_launch(void* const* d_in, const int* in_sizes, int n_in,
                              void* d_out, int out_size) {
    (void)in_sizes; (void)n_in;
    const int*   x   = (const int*)  d_in[0];
    const int*   y   = (const int*)  d_in[1];
    const float* enc = (const float*)d_in[2];
    const float* g1  = (const float*)d_in[3];
    const float* b1  = (const float*)d_in[4];
    const float* wq  = (const float*)d_in[5];
    const float* wk  = (const float*)d_in[6];
    const float* wv  = (const float*)d_in[7];
    const float* g2  = (const float*)d_in[8];
    const float* b2  = (const float*)d_in[9];
    const float* w1  = (const float*)d_in[10];
    const float* bb1 = (const float*)d_in[11];
    const float* w2  = (const float*)d_in[12];
    const float* bb2 = (const float*)d_in[13];
    float* out = (float*)d_out;

    float *z, *nll;
    float2* lse;
    __half *ylnf, *qkf, *s16, *sf, *o16, *vTf, *hf, *zf, *encf, *wtf;
    cudaGetSymbolAddress((void**)&z,   g_z);
    cudaGetSymbolAddress((void**)&nll, g_nll);
    cudaGetSymbolAddress((void**)&lse, g_lse);
    cudaGetSymbolAddress((void**)&ylnf, g_ylnf);
    cudaGetSymbolAddress((void**)&qkf, g_qkf);
    cudaGetSymbolAddress((void**)&s16, g_s16);
    cudaGetSymbolAddress((void**)&sf, g_sf);
    cudaGetSymbolAddress((void**)&o16, g_o16);
    cudaGetSymbolAddress((void**)&vTf, g_vTf);
    cudaGetSymbolAddress((void**)&hf, g_hf);
    cudaGetSymbolAddress((void**)&zf, g_zf);
    cudaGetSymbolAddress((void**)&encf, g_encf);
    cudaGetSymbolAddress((void**)&wtf, g_wtf);

    static int smem_set = 0;
    if (!smem_set) {
        cudaFuncSetAttribute(gemm_h, cudaFuncAttributeMaxDynamicSharedMemorySize,
                             NSTAGE * H_STAGE);
        smem_set = 1;
    }
    const int GH = NSTAGE * H_STAGE;

    const long DD = (long)D_MODEL * D_MODEL;
    const long SD = (long)SEQ * D_MODEL;
    const long SS = (long)SEQ * SEQ;
    const long S2 = (long)SEQ * D2;
    __half* wvTf = wtf + 2 * DD;
    __half* w1Tf = wtf + 3 * DD;
    __half* w2Tf = wtf + 4 * DD;

    dim3 tgrid(D_MODEL / 32, D_MODEL / 32, 1);
    dim3 tblk(32, 8);

    embed_kernel<<<BT, 256>>>(x, enc, z);
    transpose_half<<<tgrid, tblk>>>(wq, wtf + 0 * DD, D_MODEL, D_MODEL);
    transpose_half<<<tgrid, tblk>>>(wk, wtf + 1 * DD, D_MODEL, D_MODEL);
    transpose_half<<<tgrid, tblk>>>(wv, wvTf, D_MODEL, D_MODEL);
    transpose_half<<<tgrid, tblk>>>(w1, w1Tf, D_MODEL, D_MODEL);
    transpose_half<<<tgrid, tblk>>>(w2, w2Tf, D_MODEL, D_MODEL);
    tohalf_kernel<<<1024, 256>>>(enc, encf, (long)D_VOCAB * D_MODEL / 4);

    dim3 grid_qk  (BT / 128, D2 / 128);            // (32, 16)
    dim3 grid_proj(BT / 128, D_MODEL / 128);       // (32, 8)
    dim3 grid_attn(SEQ / 128, SEQ / 128, NB);      // (8, 8, 4)
    dim3 grid_vT  (D_MODEL / 128, SEQ / 128, NB);  // (8, 8, 4)

    for (int layer = 0; layer < NLAYERS; layer++) {
        ln_kernel<<<BT / 8, 256>>>(z, g1, b1, ylnf);

        // fused QK: [BT x 2048] = yln @ [wqT; wkT]^T -> fp16
        gemm_h<<<grid_qk, 256, GH>>>(ylnf, wtf, nullptr, nullptr, qkf,
                                     D_MODEL, D_MODEL, D2, 0, 0, 0, D_MODEL, 1.f, 8);

        // vT[d, t] = sum_k wvT[d,k] * yln[t,k]  -> fp16, per-batch
        gemm_h<<<grid_vT, 256, GH>>>(wvTf, ylnf, nullptr, nullptr, vTf,
                                     D_MODEL, D_MODEL, SEQ, 0, SD, SD, D_MODEL, 1.f, 8);

        // S = (Q K^T)/32 -> fp16
        gemm_h<<<grid_attn, 256, GH>>>(qkf, qkf + D_MODEL, nullptr, nullptr, s16,
                                       D2, D2, SEQ, S2, S2, SS, D_MODEL, 0.03125f, 8);

        softmax_kernel<<<NB * SEQ / 8, 256>>>(s16, sf);

        // O = S V -> fp16
        gemm_h<<<grid_attn, 256, GH>>>(sf, vTf, nullptr, nullptr, o16,
                                       SEQ, SEQ, D_MODEL, SS, SD, SD, SEQ, 1.f, 8);

        ln_h_kernel<<<BT / 8, 256>>>(o16, g2, b2, ylnf);

        // H = relu(Y W1 + b1) -> fp16
        gemm_h<<<grid_proj, 256, GH>>>(ylnf, w1Tf, bb1, nullptr, hf,
                                       D_MODEL, D_MODEL, D_MODEL, 0, 0, 0, D_MODEL,
                                       1.f, 8 | 4 | 1);
        // Z += H W2 + b2 -> fp32 accumulate; last layer also emits zf (fp16)
        int w2flags = 16 | 4 | 2 | ((layer == NLAYERS - 1) ? 8 : 0);
        gemm_h<<<grid_proj, 256, GH>>>(hf, w2Tf, bb2, z,
                                       (layer == NLAYERS - 1) ? zf : nullptr,
                                       D_MODEL, D_MODEL, D_MODEL, 0, 0, 0, D_MODEL,
                                       1.f, w2flags);
    }

    // logits = Z enc^T -> fp32, with fused per-colblock logsumexp partials
    dim3 grid_logits(BT / 128, D_VOCAB / 128);     // (32, 250)
    gemm_h<<<grid_logits, 256, GH>>>(zf, encf, nullptr, out, nullptr,
                                     D_MODEL, D_MODEL, D_VOCAB, 0, 0, 0, D_MODEL,
                                     1.f, 16 | 32);

    nll_final<<<BT, 256>>>(lse, out, y, nll);
    if ((long)out_size > BTV)
        loss_reduce_kernel<<<1, 256>>>(nll, out, BTV);
}

// round 16
// speedup vs baseline: 1.0174x; 1.0174x over previous
#include <cuda_runtime.h>
#include <cuda_fp16.h>
#include <cstdint>
#include <math.h>

#define D_MODEL 1024
#define D_VOCAB 32000
#define NB 4
#define SEQ 1024
#define BT (NB * SEQ)
#define NLAYERS 6
#define BTV ((long)BT * D_VOCAB)
#define D2 (2 * D_MODEL)
#define LSE_NB (D_VOCAB / 128)

// ---------------- scratch (device globals) ----------------------------------
__device__ float g_z [BT * D_MODEL];
__device__ float g_nll[BT];
__device__ float2 g_lse[(long)BT * LSE_NB];

__device__ __half g_ylnf[BT * D_MODEL];
__device__ __half g_qkf [BT * D2];
__device__ __half g_s16 [NB * SEQ * SEQ];
__device__ __half g_sf  [NB * SEQ * SEQ];
__device__ __half g_o16 [BT * D_MODEL];
__device__ __half g_vTf [BT * D_MODEL];
__device__ __half g_hf  [BT * D_MODEL];
__device__ __half g_zf  [BT * D_MODEL];
__device__ __half g_encf[(long)D_VOCAB * D_MODEL];
__device__ __half g_wtf [5 * D_MODEL * D_MODEL];   // wqT wkT wvT w1T w2T

// ---------------- helpers ----------------------------------------------------
__device__ __forceinline__ uint32_t smem_u32(const void* p) {
    uint32_t a;
    asm("{ .reg .u64 t; cvta.to.shared.u64 t, %1; cvt.u32.u64 %0, t; }" : "=r"(a) : "l"(p));
    return a;
}
__device__ __forceinline__ void ldsm4(uint32_t addr, uint32_t& r0, uint32_t& r1,
                                      uint32_t& r2, uint32_t& r3) {
    asm volatile("ldmatrix.sync.aligned.m8n8.x4.shared.b16 {%0,%1,%2,%3}, [%4];"
                 : "=r"(r0), "=r"(r1), "=r"(r2), "=r"(r3) : "r"(addr));
}
__device__ __forceinline__ void mma_fp16(float* c, uint32_t a0, uint32_t a1,
                                         uint32_t a2, uint32_t a3,
                                         uint32_t b0, uint32_t b1) {
    asm volatile(
        "mma.sync.aligned.m16n8k16.row.col.f32.f16.f16.f32 "
        "{%0,%1,%2,%3}, {%4,%5,%6,%7}, {%8,%9}, {%0,%1,%2,%3};"
        : "+f"(c[0]), "+f"(c[1]), "+f"(c[2]), "+f"(c[3])
        : "r"(a0), "r"(a1), "r"(a2), "r"(a3), "r"(b0), "r"(b1));
}
#define CP16(dst, src) \
    asm volatile("cp.async.cg.shared.global [%0], [%1], 16;" :: "r"(dst), "l"(src))
#define CP_COMMIT() asm volatile("cp.async.commit_group;" ::: "memory")
#define CP_WAIT1()  asm volatile("cp.async.wait_group 1;" ::: "memory")

template <int OP>
__device__ __forceinline__ float warp_red(float v) {
    #pragma unroll
    for (int o = 16; o; o >>= 1) {
        float t = __shfl_xor_sync(0xffffffffu, v, o);
        v = OP ? fmaxf(v, t) : v + t;
    }
    return v;
}
__device__ __forceinline__ void h2f(uint32_t u, float& a, float& b) {
    __half2 h = *(__half2*)&u;
    float2 f = __half22float2(h);
    a = f.x; b = f.y;
}

// ---------------- fp16 single-pass GEMM NT (K-tile 32, NSTAGE 3) -------------
// flags: 1=relu 2=accum-C-fp32 4=bias 8=fp16-out(Cf) 16=fp32-out(C) 32=LSE partials
#define H_STAGE 16384
#define NSTAGE 3
__global__ __launch_bounds__(256, 2) void gemm_h(
    const __half* __restrict__ A, const __half* __restrict__ B,
    const float* __restrict__ bias, float* __restrict__ C,
    __half* __restrict__ Cf,
    int lda, int ldb, int ldc, long sA, long sB, long sC,
    int K, float alpha, int flags) {

    extern __shared__ __align__(16) uint8_t sm[];

    A += (long)blockIdx.z * sA;
    B += (long)blockIdx.z * sB;
    if (C)  C  += (long)blockIdx.z * sC;
    if (Cf) Cf += (long)blockIdx.z * sC;

    const int tid  = threadIdx.x;
    const int wid  = tid >> 5;
    const int lane = tid & 31;
    const int warp_m = wid & 3;
    const int warp_n = wid >> 2;
    const int row0 = blockIdx.x * 128;
    const int col0 = blockIdx.y * 128;

    const uint32_t sbase = smem_u32(sm);

    const int lr = tid >> 1;
    const int lq = tid & 1;
    const int swz = (lr >> 1) & 3;
    const __half* Ap = A + (long)(row0 + lr) * lda;
    const __half* Bp = B + (long)(col0 + lr) * ldb;

    float acc[2][8][4];
    #pragma unroll
    for (int mb = 0; mb < 2; mb++)
        #pragma unroll
        for (int nb = 0; nb < 8; nb++)
            #pragma unroll
            for (int i = 0; i < 4; i++) acc[mb][nb][i] = 0.f;

    auto load_tile = [&](int kt, int st) {
        int k0 = kt << 5;
        uint32_t sb = sbase + st * H_STAGE;
        #pragma unroll
        for (int j = 0; j < 2; j++) {
            int c = lq * 2 + j;
            uint32_t off = (uint32_t)(lr * 64 + (c ^ swz) * 16);
            CP16(sb + off,        Ap + k0 + c * 8);
            CP16(sb + 8192 + off, Bp + k0 + c * 8);
        }
    };

    const int KT = K >> 5;
    load_tile(0, 0); CP_COMMIT();
    if (KT > 1) { load_tile(1, 1); CP_COMMIT(); }
    else        { CP_COMMIT(); }

    for (int kt = 0; kt < KT; kt++) {
        CP_WAIT1();
        __syncthreads();
        if (kt + 2 < KT) load_tile(kt + 2, (kt + 2) % NSTAGE);
        CP_COMMIT();

        uint32_t sb = sbase + (kt % NSTAGE) * H_STAGE;
        #pragma unroll
        for (int kc = 0; kc < 2; kc++) {
            const int chunkA = kc * 2 + (lane >> 4);
            uint32_t ah[2][4];
            #pragma unroll
            for (int mb = 0; mb < 2; mb++) {
                int mrow = warp_m * 32 + mb * 16 + (lane & 15);
                uint32_t off = (uint32_t)(mrow * 64 + (chunkA ^ ((mrow >> 1) & 3)) * 16);
                ldsm4(sb + off, ah[mb][0], ah[mb][1], ah[mb][2], ah[mb][3]);
            }
            #pragma unroll
            for (int nb4 = 0; nb4 < 4; nb4++) {
                int nrow = warp_n * 64 + nb4 * 16 + (lane & 15);
                uint32_t off = (uint32_t)(nrow * 64 + (chunkA ^ ((nrow >> 1) & 3)) * 16);
                uint32_t b0, b1, b2, b3;
                ldsm4(sb + 8192 + off, b0, b1, b2, b3);
                #pragma unroll
                for (int mb = 0; mb < 2; mb++) {
                    mma_fp16(acc[mb][nb4 * 2],     ah[mb][0], ah[mb][1], ah[mb][2], ah[mb][3], b0, b2);
                    mma_fp16(acc[mb][nb4 * 2 + 1], ah[mb][0], ah[mb][1], ah[mb][2], ah[mb][3], b1, b3);
                }
            }
        }
    }

    #pragma unroll
    for (int mb = 0; mb < 2; mb++) {
        #pragma unroll
        for (int nb = 0; nb < 8; nb++) {
            int m0 = row0 + warp_m * 32 + mb * 16 + (lane >> 2);
            int n0 = col0 + warp_n * 64 + nb * 8 + (lane & 3) * 2;
            #pragma unroll
            for (int half = 0; half < 2; half++) {
                int m = m0 + half * 8;
                float v0 = acc[mb][nb][half * 2 + 0] * alpha;
                float v1 = acc[mb][nb][half * 2 + 1] * alpha;
                if (flags & 4) { v0 += bias[n0]; v1 += bias[n0 + 1]; }
                if (flags & 1) { v0 = fmaxf(v0, 0.f); v1 = fmaxf(v1, 0.f); }
                long idx = (long)m * ldc + n0;
                if (flags & 2) { float2 o = *(float2*)(C + idx); v0 += o.x; v1 += o.y; }
                if (flags & 16) *(float2*)(C + idx) = make_float2(v0, v1);
                if (flags & 8)  *(__half2*)(Cf + idx) = __floats2half2_rn(v0, v1);
            }
        }
    }

    if (flags & 32) {
        __shared__ float2 lse_sh[128];
        float msm[2][2], mss[2][2];
        #pragma unroll
        for (int mb = 0; mb < 2; mb++) {
            #pragma unroll
            for (int half = 0; half < 2; half++) {
                float lm = -1e30f;
                #pragma unroll
                for (int nb = 0; nb < 8; nb++)
                    lm = fmaxf(lm, fmaxf(acc[mb][nb][half * 2], acc[mb][nb][half * 2 + 1]));
                float ls = 0.f;
                #pragma unroll
                for (int nb = 0; nb < 8; nb++)
                    ls += expf(acc[mb][nb][half * 2] - lm) +
                          expf(acc[mb][nb][half * 2 + 1] - lm);
                #pragma unroll
                for (int o = 1; o <= 2; o <<= 1) {
                    float m2 = __shfl_xor_sync(0xffffffffu, lm, o);
                    float s2 = __shfl_xor_sync(0xffffffffu, ls, o);
                    float M = fmaxf(lm, m2);
                    ls = ls * expf(lm - M) + s2 * expf(m2 - M);
                    lm = M;
                }
                msm[mb][half] = lm; mss[mb][half] = ls;
                int lrow = warp_m * 32 + mb * 16 + half * 8 + (lane >> 2);
                if (warp_n == 1 && (lane & 3) == 0)
                    lse_sh[lrow] = make_float2(lm, ls);
            }
        }
        __syncthreads();
        if (warp_n == 0 && (lane & 3) == 0) {
            float2* lse = g_lse;
            #pragma unroll
            for (int mb = 0; mb < 2; mb++) {
                #pragma unroll
                for (int half = 0; half < 2; half++) {
                    int lrow = warp_m * 32 + mb * 16 + half * 8 + (lane >> 2);
                    float2 o = lse_sh[lrow];
                    float M = fmaxf(msm[mb][half], o.x);
                    float S = mss[mb][half] * expf(msm[mb][half] - M) +
                              o.y * expf(o.x - M);
                    lse[(long)(row0 + lrow) * gridDim.y + blockIdx.y] = make_float2(M, S);
                }
            }
        }
    }
}

// ---------------- transpose + fp32->fp16 -------------------------------------
__global__ void transpose_half(const float* __restrict__ src, __half* __restrict__ dst,
                               int R, int Ccols) {
    __shared__ float t[32][33];
    long ofs = (long)blockIdx.z * R * Ccols;
    src += ofs; dst += ofs;
    int bx = blockIdx.x * 32, by = blockIdx.y * 32;
    int x = bx + threadIdx.x;
    #pragma unroll
    for (int j = 0; j < 32; j += 8) {
        int y = by + threadIdx.y + j;
        t[threadIdx.y + j][threadIdx.x] = src[(long)y * Ccols + x];
    }
    __syncthreads();
    x = by + threadIdx.x;
    #pragma unroll
    for (int j = 0; j < 32; j += 8) {
        int y = bx + threadIdx.y + j;
        dst[(long)y * R + x] = __float2half_rn(t[threadIdx.x][threadIdx.y + j]);
    }
}

// ---------------- fp32 -> fp16 convert ---------------------------------------
__global__ void tohalf_kernel(const float* __restrict__ src, __half* __restrict__ dst,
                              long n4) {
    long i = (long)blockIdx.x * blockDim.x + threadIdx.x;
    long stride = (long)gridDim.x * blockDim.x;
    for (; i < n4; i += stride) {
        float4 v = ((const float4*)src)[i];
        ((__half2*)dst)[i * 2]     = __floats2half2_rn(v.x, v.y);
        ((__half2*)dst)[i * 2 + 1] = __floats2half2_rn(v.z, v.w);
    }
}

// ---------------- embedding gather ------------------------------------------
__global__ void embed_kernel(const int* __restrict__ x, const float* __restrict__ enc,
                             float* __restrict__ z) {
    int row = blockIdx.x;
    int tok = x[row];
    const float4* src = (const float4*)(enc + (long)tok * D_MODEL);
    float4* dst = (float4*)(z + (long)row * D_MODEL);
    for (int i = threadIdx.x; i < D_MODEL / 4; i += blockDim.x) dst[i] = src[i];
}

// ---------------- (buggy) LayerNorm, warp-per-row, fp32 input ----------------
__global__ __launch_bounds__(256) void ln_kernel(
    const float* __restrict__ in, const float* __restrict__ gamma,
    const float* __restrict__ beta, __half* __restrict__ outf) {
    int row  = blockIdx.x * 8 + (threadIdx.x >> 5);
    int lane = threadIdx.x & 31;
    const float4* xr = (const float4*)(in + (long)row * D_MODEL);

    float4 xv[8];
    float s = 0.f, s2 = 0.f;
    #pragma unroll
    for (int j = 0; j < 8; j++) {
        xv[j] = xr[lane + 32 * j];
        s  += xv[j].x + xv[j].y + xv[j].z + xv[j].w;
        s2 += xv[j].x * xv[j].x + xv[j].y * xv[j].y
            + xv[j].z * xv[j].z + xv[j].w * xv[j].w;
    }
    float S  = warp_red<0>(s);
    float S2 = warp_red<0>(s2);
    float mu  = S * (1.f / (float)D_MODEL);
    float var = (S2 - (float)D_MODEL * mu * mu) * (1.f / (float)(D_MODEL - 1));
    float shift = mu * rsqrtf(var);

    #pragma unroll
    for (int j = 0; j < 8; j++) {
        float4 g = ((const float4*)gamma)[lane + 32 * j];
        float4 b = ((const float4*)beta)[lane + 32 * j];
        long base = (long)row * D_MODEL + (lane + 32 * j) * 4;
        *(__half2*)(outf + base)     = __floats2half2_rn((xv[j].x - shift) * g.x + b.x,
                                                         (xv[j].y - shift) * g.y + b.y);
        *(__half2*)(outf + base + 2) = __floats2half2_rn((xv[j].z - shift) * g.z + b.z,
                                                         (xv[j].w - shift) * g.w + b.w);
    }
}

// ---------------- (buggy) LayerNorm, warp-per-row, fp16 input ----------------
__global__ __launch_bounds__(256) void ln_h_kernel(
    const __half* __restrict__ in, const float* __restrict__ gamma,
    const float* __restrict__ beta, __half* __restrict__ outf) {
    int row  = blockIdx.x * 8 + (threadIdx.x >> 5);
    int lane = threadIdx.x & 31;
    const uint4* xr = (const uint4*)(in + (long)row * D_MODEL);

    float f[32];
    float s = 0.f, s2 = 0.f;
    #pragma unroll
    for (int j = 0; j < 4; j++) {
        uint4 r = xr[lane + 32 * j];
        h2f(r.x, f[j*8+0], f[j*8+1]); h2f(r.y, f[j*8+2], f[j*8+3]);
        h2f(r.z, f[j*8+4], f[j*8+5]); h2f(r.w, f[j*8+6], f[j*8+7]);
        #pragma unroll
        for (int k = 0; k < 8; k++) { s += f[j*8+k]; s2 += f[j*8+k] * f[j*8+k]; }
    }
    float S  = warp_red<0>(s);
    float S2 = warp_red<0>(s2);
    float mu  = S * (1.f / (float)D_MODEL);
    float var = (S2 - (float)D_MODEL * mu * mu) * (1.f / (float)(D_MODEL - 1));
    float shift = mu * rsqrtf(var);

    #pragma unroll
    for (int j = 0; j < 4; j++) {
        long base = (long)row * D_MODEL + (lane + 32 * j) * 8;
        #pragma unroll
        for (int t = 0; t < 2; t++) {
            float4 g = ((const float4*)gamma)[(lane + 32 * j) * 2 + t];
            float4 b = ((const float4*)beta)[(lane + 32 * j) * 2 + t];
            int o = j * 8 + t * 4;
            *(__half2*)(outf + base + t * 4)     = __floats2half2_rn((f[o+0] - shift) * g.x + b.x,
                                                                     (f[o+1] - shift) * g.y + b.y);
            *(__half2*)(outf + base + t * 4 + 2) = __floats2half2_rn((f[o+2] - shift) * g.z + b.z,
                                                                     (f[o+3] - shift) * g.w + b.w);
        }
    }
}

// ---------------- softmax, warp-per-row, fp16 in/out --------------------------
__global__ __launch_bounds__(256) void softmax_kernel(
    const __half* __restrict__ s, __half* __restrict__ outf) {
    int row  = blockIdx.x * 8 + (threadIdx.x >> 5);
    int lane = threadIdx.x & 31;
    const uint4* r4 = (const uint4*)(s + (long)row * SEQ);

    float f[32];
    float m = -1e30f;
    #pragma unroll
    for (int j = 0; j < 4; j++) {
        uint4 r = r4[lane + 32 * j];
        h2f(r.x, f[j*8+0], f[j*8+1]); h2f(r.y, f[j*8+2], f[j*8+3]);
        h2f(r.z, f[j*8+4], f[j*8+5]); h2f(r.w, f[j*8+6], f[j*8+7]);
        #pragma unroll
        for (int k = 0; k < 8; k++) m = fmaxf(m, f[j*8+k]);
    }
    float mx = warp_red<1>(m);

    float sum = 0.f;
    #pragma unroll
    for (int j = 0; j < 32; j++) { f[j] = expf(f[j] - mx); sum += f[j]; }
    float inv = 1.f / warp_red<0>(sum);

    #pragma unroll
    for (int j = 0; j < 4; j++) {
        long base = (long)row * SEQ + (lane + 32 * j) * 8;
        #pragma unroll
        for (int t = 0; t < 4; t++)
            *(__half2*)(outf + base + t * 2) =
                __floats2half2_rn(f[j*8 + t*2] * inv, f[j*8 + t*2 + 1] * inv);
    }
}

// ---------------- final NLL from per-colblock LSE partials -------------------
__global__ void nll_final(const float2* __restrict__ lse,
                          const float* __restrict__ logits,
                          const int* __restrict__ y, float* __restrict__ nll) {
    int row = blockIdx.x;
    int tid = threadIdx.x;

    float m = -1e30f, s = 0.f;
    if (tid < LSE_NB) {
        float2 p = lse[(long)row * LSE_NB + tid];
        m = p.x; s = p.y;
    }

    int lane = tid & 31, wid = tid >> 5;
    #pragma unroll
    for (int o = 16; o; o >>= 1) {
        float m2 = __shfl_xor_sync(0xffffffffu, m, o);
        float s2 = __shfl_xor_sync(0xffffffffu, s, o);
        float M = fmaxf(m, m2);
        s = s * expf(m - M) + s2 * expf(m2 - M);
        m = M;
    }
    __shared__ float sm_[8], ss_[8];
    if (lane == 0) { sm_[wid] = m; ss_[wid] = s; }
    __syncthreads();
    if (tid == 0) {
        float M = sm_[0];
        #pragma unroll
        for (int i = 1; i < 8; i++) M = fmaxf(M, sm_[i]);
        float S = 0.f;
        #pragma unroll
        for (int i = 0; i < 8; i++) S += ss_[i] * expf(sm_[i] - M);
        nll[row] = (M + logf(S)) - logits[(long)row * D_VOCAB + y[row]];
    }
}

__global__ void loss_reduce_kernel(const float* __restrict__ nll, float* __restrict__ out,
                                   long ofs) {
    __shared__ float red[256];
    int tid = threadIdx.x;
    float s = 0.f;
    for (int i = tid; i < BT; i += 256) s += nll[i];
    red[tid] = s; __syncthreads();
    #pragma unroll
    for (int o = 128; o > 0; o >>= 1) { if (tid < o) red[tid] += red[tid + o]; __syncthreads(); }
    if (tid == 0) out[ofs] = red[0] / (float)BT;
}

// ---------------- driver -----------------------------------------------------
extern "C" void kernel_launch(void* const* d_in, const int* in_sizes, int n_in,
                              void* d_out, int out_size) {
    (void)in_sizes; (void)n_in;
    const int*   x   = (const int*)  d_in[0];
    const int*   y   = (const int*)  d_in[1];
    const float* enc = (const float*)d_in[2];
    const float* g1  = (const float*)d_in[3];
    const float* b1  = (const float*)d_in[4];
    const float* wq  = (const float*)d_in[5];
    const float* wk  = (const float*)d_in[6];
    const float* wv  = (const float*)d_in[7];
    const float* g2  = (const float*)d_in[8];
    const float* b2  = (const float*)d_in[9];
    const float* w1  = (const float*)d_in[10];
    const float* bb1 = (const float*)d_in[11];
    const float* w2  = (const float*)d_in[12];
    const float* bb2 = (const float*)d_in[13];
    float* out = (float*)d_out;

    float *z, *nll;
    float2* lse;
    __half *ylnf, *qkf, *s16, *sf, *o16, *vTf, *hf, *zf, *encf, *wtf;
    cudaGetSymbolAddress((void**)&z,   g_z);
    cudaGetSymbolAddress((void**)&nll, g_nll);
    cudaGetSymbolAddress((void**)&lse, g_lse);
    cudaGetSymbolAddress((void**)&ylnf, g_ylnf);
    cudaGetSymbolAddress((void**)&qkf, g_qkf);
    cudaGetSymbolAddress((void**)&s16, g_s16);
    cudaGetSymbolAddress((void**)&sf, g_sf);
    cudaGetSymbolAddress((void**)&o16, g_o16);
    cudaGetSymbolAddress((void**)&vTf, g_vTf);
    cudaGetSymbolAddress((void**)&hf, g_hf);
    cudaGetSymbolAddress((void**)&zf, g_zf);
    cudaGetSymbolAddress((void**)&encf, g_encf);
    cudaGetSymbolAddress((void**)&wtf, g_wtf);

    static int inited = 0;
    static cudaStream_t s2 = 0;
    static cudaEvent_t evRoot = 0, evF = 0, evJ = 0, evEnc = 0;
    if (!inited) {
        cudaFuncSetAttribute(gemm_h, cudaFuncAttributeMaxDynamicSharedMemorySize,
                             NSTAGE * H_STAGE);
        cudaStreamCreateWithFlags(&s2, cudaStreamNonBlocking);
        cudaEventCreateWithFlags(&evRoot, cudaEventDisableTiming);
        cudaEventCreateWithFlags(&evF,    cudaEventDisableTiming);
        cudaEventCreateWithFlags(&evJ,    cudaEventDisableTiming);
        cudaEventCreateWithFlags(&evEnc,  cudaEventDisableTiming);
        inited = 1;
    }
    const int GH = NSTAGE * H_STAGE;

    const long DD = (long)D_MODEL * D_MODEL;
    const long SD = (long)SEQ * D_MODEL;
    const long SS = (long)SEQ * SEQ;
    const long S2L = (long)SEQ * D2;
    __half* wvTf = wtf + 2 * DD;
    __half* w1Tf = wtf + 3 * DD;
    __half* w2Tf = wtf + 4 * DD;

    dim3 tgrid(D_MODEL / 32, D_MODEL / 32, 1);
    dim3 tblk(32, 8);

    embed_kernel<<<BT, 256>>>(x, enc, z);
    transpose_half<<<tgrid, tblk>>>(wq, wtf + 0 * DD, D_MODEL, D_MODEL);
    transpose_half<<<tgrid, tblk>>>(wk, wtf + 1 * DD, D_MODEL, D_MODEL);
    transpose_half<<<tgrid, tblk>>>(wv, wvTf, D_MODEL, D_MODEL);
    transpose_half<<<tgrid, tblk>>>(w1, w1Tf, D_MODEL, D_MODEL);
    transpose_half<<<tgrid, tblk>>>(w2, w2Tf, D_MODEL, D_MODEL);

    // fork: enc -> fp16 runs on side stream, overlapped with the layer stack
    cudaEventRecord(evRoot, 0);
    cudaStreamWaitEvent(s2, evRoot, 0);
    tohalf_kernel<<<1024, 256, 0, s2>>>(enc, encf, (long)D_VOCAB * D_MODEL / 4);
    cudaEventRecord(evEnc, s2);

    dim3 grid_qk  (BT / 128, D2 / 128);            // (32, 16)
    dim3 grid_proj(BT / 128, D_MODEL / 128);       // (32, 8)
    dim3 grid_attn(SEQ / 128, SEQ / 128, NB);      // (8, 8, 4)
    dim3 grid_vT  (D_MODEL / 128, SEQ / 128, NB);  // (8, 8, 4)

    for (int layer = 0; layer < NLAYERS; layer++) {
        ln_kernel<<<BT / 8, 256>>>(z, g1, b1, ylnf);

        // fork: vT GEMM on side stream, concurrent with QK -> S -> softmax
        cudaEventRecord(evF, 0);
        cudaStreamWaitEvent(s2, evF, 0);
        gemm_h<<<grid_vT, 256, GH, s2>>>(wvTf, ylnf, nullptr, nullptr, vTf,
                                         D_MODEL, D_MODEL, SEQ, 0, SD, SD, D_MODEL, 1.f, 8);
        cudaEventRecord(evJ, s2);

        // fused QK: [BT x 2048] = yln @ [wqT; wkT]^T -> fp16
        gemm_h<<<grid_qk, 256, GH>>>(ylnf, wtf, nullptr, nullptr, qkf,
                                     D_MODEL, D_MODEL, D2, 0, 0, 0, D_MODEL, 1.f, 8);

        // S = (Q K^T)/32 -> fp16
        gemm_h<<<grid_attn, 256, GH>>>(qkf, qkf + D_MODEL, nullptr, nullptr, s16,
                                       D2, D2, SEQ, S2L, S2L, SS, D_MODEL, 0.03125f, 8);

        softmax_kernel<<<NB * SEQ / 8, 256>>>(s16, sf);

        // join vT, then O = S V -> fp16
        cudaStreamWaitEvent(0, evJ, 0);
        gemm_h<<<grid_attn, 256, GH>>>(sf, vTf, nullptr, nullptr, o16,
                                       SEQ, SEQ, D_MODEL, SS, SD, SD, SEQ, 1.f, 8);

        ln_h_kernel<<<BT / 8, 256>>>(o16, g2, b2, ylnf);

        gemm_h<<<grid_proj, 256, GH>>>(ylnf, w1Tf, bb1, nullptr, hf,
                                       D_MODEL, D_MODEL, D_MODEL, 0, 0, 0, D_MODEL,
                                       1.f, 8 | 4 | 1);
        int w2flags = 16 | 4 | 2 | ((layer == NLAYERS - 1) ? 8 : 0);
        gemm_h<<<grid_proj, 256, GH>>>(hf, w2Tf, bb2, z,
                                       (layer == NLAYERS - 1) ? zf : nullptr,
                                       D_MODEL, D_MODEL, D_MODEL, 0, 0, 0, D_MODEL,
                                       1.f, w2flags);
    }

    // join enc convert before logits
    cudaStreamWaitEvent(0, evEnc, 0);
    dim3 grid_logits(BT / 128, D_VOCAB / 128);     // (32, 250)
    gemm_h<<<grid_logits, 256, GH>>>(zf, encf, nullptr, out, nullptr,
                                     D_MODEL, D_MODEL, D_VOCAB, 0, 0, 0, D_MODEL,
                                     1.f, 16 | 32);

    nll_final<<<BT, 256>>>(lse, out, y, nll);
    if ((long)out_size > BTV)
        loss_reduce_kernel<<<1, 256>>>(nll, out, BTV);
}

// round 17
// speedup vs baseline: 1.0435x; 1.0257x over previous
#include <cuda_runtime.h>
#include <cuda_fp16.h>
#include <cstdint>
#include <math.h>

#define D_MODEL 1024
#define D_VOCAB 32000
#define NB 4
#define SEQ 1024
#define BT (NB * SEQ)
#define NLAYERS 6
#define BTV ((long)BT * D_VOCAB)
#define D2 (2 * D_MODEL)
#define LSE_NB (D_VOCAB / 128)

// ---------------- scratch (device globals) ----------------------------------
__device__ float g_z [BT * D_MODEL];
__device__ float g_nll[BT];
__device__ float2 g_lse[(long)BT * LSE_NB];

__device__ __half g_ylnf[BT * D_MODEL];
__device__ __half g_qkf [BT * D2];
__device__ __half g_s16 [NB * SEQ * SEQ];
__device__ __half g_sf  [NB * SEQ * SEQ];
__device__ __half g_o16 [BT * D_MODEL];
__device__ __half g_vTf [BT * D_MODEL];
__device__ __half g_hf  [BT * D_MODEL];
__device__ __half g_zf  [BT * D_MODEL];
__device__ __half g_encf[(long)D_VOCAB * D_MODEL];
__device__ __half g_wtf [5 * D_MODEL * D_MODEL];   // wqT wkT wvT w1T w2T

// ---------------- helpers ----------------------------------------------------
__device__ __forceinline__ uint32_t smem_u32(const void* p) {
    uint32_t a;
    asm("{ .reg .u64 t; cvta.to.shared.u64 t, %1; cvt.u32.u64 %0, t; }" : "=r"(a) : "l"(p));
    return a;
}
__device__ __forceinline__ void ldsm4(uint32_t addr, uint32_t& r0, uint32_t& r1,
                                      uint32_t& r2, uint32_t& r3) {
    asm volatile("ldmatrix.sync.aligned.m8n8.x4.shared.b16 {%0,%1,%2,%3}, [%4];"
                 : "=r"(r0), "=r"(r1), "=r"(r2), "=r"(r3) : "r"(addr));
}
__device__ __forceinline__ void mma_fp16(float* c, uint32_t a0, uint32_t a1,
                                         uint32_t a2, uint32_t a3,
                                         uint32_t b0, uint32_t b1) {
    asm volatile(
        "mma.sync.aligned.m16n8k16.row.col.f32.f16.f16.f32 "
        "{%0,%1,%2,%3}, {%4,%5,%6,%7}, {%8,%9}, {%0,%1,%2,%3};"
        : "+f"(c[0]), "+f"(c[1]), "+f"(c[2]), "+f"(c[3])
        : "r"(a0), "r"(a1), "r"(a2), "r"(a3), "r"(b0), "r"(b1));
}
#define CP16(dst, src) \
    asm volatile("cp.async.cg.shared.global [%0], [%1], 16;" :: "r"(dst), "l"(src))
#define CP_COMMIT() asm volatile("cp.async.commit_group;" ::: "memory")
#define CP_WAIT1()  asm volatile("cp.async.wait_group 1;" ::: "memory")

template <int OP>
__device__ __forceinline__ float warp_red(float v) {
    #pragma unroll
    for (int o = 16; o; o >>= 1) {
        float t = __shfl_xor_sync(0xffffffffu, v, o);
        v = OP ? fmaxf(v, t) : v + t;
    }
    return v;
}
__device__ __forceinline__ void h2f(uint32_t u, float& a, float& b) {
    __half2 h = *(__half2*)&u;
    float2 f = __half22float2(h);
    a = f.x; b = f.y;
}

// ---------------- fp16 single-pass GEMM NT (K-tile 32, NSTAGE 3) -------------
// flags: 1=relu 2=accum-C-fp32 4=bias 8=fp16-out(Cf) 16=fp32-out(C) 32=LSE partials
#define H_STAGE 16384
#define NSTAGE 3
__global__ __launch_bounds__(256, 2) void gemm_h(
    const __half* __restrict__ A, const __half* __restrict__ B,
    const float* __restrict__ bias, float* __restrict__ C,
    __half* __restrict__ Cf,
    int lda, int ldb, int ldc, long sA, long sB, long sC,
    int K, float alpha, int flags) {

    extern __shared__ __align__(16) uint8_t sm[];

    A += (long)blockIdx.z * sA;
    B += (long)blockIdx.z * sB;
    if (C)  C  += (long)blockIdx.z * sC;
    if (Cf) Cf += (long)blockIdx.z * sC;

    const int tid  = threadIdx.x;
    const int wid  = tid >> 5;
    const int lane = tid & 31;
    const int warp_m = wid & 3;
    const int warp_n = wid >> 2;
    const int row0 = blockIdx.x * 128;
    const int col0 = blockIdx.y * 128;

    const uint32_t sbase = smem_u32(sm);

    const int lr = tid >> 1;
    const int lq = tid & 1;
    const int swz = (lr >> 1) & 3;
    const __half* Ap = A + (long)(row0 + lr) * lda;
    const __half* Bp = B + (long)(col0 + lr) * ldb;

    float acc[2][8][4];
    #pragma unroll
    for (int mb = 0; mb < 2; mb++)
        #pragma unroll
        for (int nb = 0; nb < 8; nb++)
            #pragma unroll
            for (int i = 0; i < 4; i++) acc[mb][nb][i] = 0.f;

    auto load_tile = [&](int kt, int st) {
        int k0 = kt << 5;
        uint32_t sb = sbase + st * H_STAGE;
        #pragma unroll
        for (int j = 0; j < 2; j++) {
            int c = lq * 2 + j;
            uint32_t off = (uint32_t)(lr * 64 + (c ^ swz) * 16);
            CP16(sb + off,        Ap + k0 + c * 8);
            CP16(sb + 8192 + off, Bp + k0 + c * 8);
        }
    };

    const int KT = K >> 5;
    load_tile(0, 0); CP_COMMIT();
    if (KT > 1) { load_tile(1, 1); CP_COMMIT(); }
    else        { CP_COMMIT(); }

    for (int kt = 0; kt < KT; kt++) {
        CP_WAIT1();
        __syncthreads();
        if (kt + 2 < KT) load_tile(kt + 2, (kt + 2) % NSTAGE);
        CP_COMMIT();

        uint32_t sb = sbase + (kt % NSTAGE) * H_STAGE;
        #pragma unroll
        for (int kc = 0; kc < 2; kc++) {
            const int chunkA = kc * 2 + (lane >> 4);
            uint32_t ah[2][4];
            #pragma unroll
            for (int mb = 0; mb < 2; mb++) {
                int mrow = warp_m * 32 + mb * 16 + (lane & 15);
                uint32_t off = (uint32_t)(mrow * 64 + (chunkA ^ ((mrow >> 1) & 3)) * 16);
                ldsm4(sb + off, ah[mb][0], ah[mb][1], ah[mb][2], ah[mb][3]);
            }
            #pragma unroll
            for (int nb4 = 0; nb4 < 4; nb4++) {
                int nrow = warp_n * 64 + nb4 * 16 + (lane & 15);
                uint32_t off = (uint32_t)(nrow * 64 + (chunkA ^ ((nrow >> 1) & 3)) * 16);
                uint32_t b0, b1, b2, b3;
                ldsm4(sb + 8192 + off, b0, b1, b2, b3);
                #pragma unroll
                for (int mb = 0; mb < 2; mb++) {
                    mma_fp16(acc[mb][nb4 * 2],     ah[mb][0], ah[mb][1], ah[mb][2], ah[mb][3], b0, b2);
                    mma_fp16(acc[mb][nb4 * 2 + 1], ah[mb][0], ah[mb][1], ah[mb][2], ah[mb][3], b1, b3);
                }
            }
        }
    }

    #pragma unroll
    for (int mb = 0; mb < 2; mb++) {
        #pragma unroll
        for (int nb = 0; nb < 8; nb++) {
            int m0 = row0 + warp_m * 32 + mb * 16 + (lane >> 2);
            int n0 = col0 + warp_n * 64 + nb * 8 + (lane & 3) * 2;
            #pragma unroll
            for (int half = 0; half < 2; half++) {
                int m = m0 + half * 8;
                float v0 = acc[mb][nb][half * 2 + 0] * alpha;
                float v1 = acc[mb][nb][half * 2 + 1] * alpha;
                if (flags & 4) { v0 += bias[n0]; v1 += bias[n0 + 1]; }
                if (flags & 1) { v0 = fmaxf(v0, 0.f); v1 = fmaxf(v1, 0.f); }
                long idx = (long)m * ldc + n0;
                if (flags & 2) { float2 o = *(float2*)(C + idx); v0 += o.x; v1 += o.y; }
                if (flags & 16) *(float2*)(C + idx) = make_float2(v0, v1);
                if (flags & 8)  *(__half2*)(Cf + idx) = __floats2half2_rn(v0, v1);
            }
        }
    }

    if (flags & 32) {
        __shared__ float2 lse_sh[128];
        float msm[2][2], mss[2][2];
        #pragma unroll
        for (int mb = 0; mb < 2; mb++) {
            #pragma unroll
            for (int half = 0; half < 2; half++) {
                float lm = -1e30f;
                #pragma unroll
                for (int nb = 0; nb < 8; nb++)
                    lm = fmaxf(lm, fmaxf(acc[mb][nb][half * 2], acc[mb][nb][half * 2 + 1]));
                float ls = 0.f;
                #pragma unroll
                for (int nb = 0; nb < 8; nb++)
                    ls += expf(acc[mb][nb][half * 2] - lm) +
                          expf(acc[mb][nb][half * 2 + 1] - lm);
                #pragma unroll
                for (int o = 1; o <= 2; o <<= 1) {
                    float m2 = __shfl_xor_sync(0xffffffffu, lm, o);
                    float s2 = __shfl_xor_sync(0xffffffffu, ls, o);
                    float M = fmaxf(lm, m2);
                    ls = ls * expf(lm - M) + s2 * expf(m2 - M);
                    lm = M;
                }
                msm[mb][half] = lm; mss[mb][half] = ls;
                int lrow = warp_m * 32 + mb * 16 + half * 8 + (lane >> 2);
                if (warp_n == 1 && (lane & 3) == 0)
                    lse_sh[lrow] = make_float2(lm, ls);
            }
        }
        __syncthreads();
        if (warp_n == 0 && (lane & 3) == 0) {
            float2* lse = g_lse;
            #pragma unroll
            for (int mb = 0; mb < 2; mb++) {
                #pragma unroll
                for (int half = 0; half < 2; half++) {
                    int lrow = warp_m * 32 + mb * 16 + half * 8 + (lane >> 2);
                    float2 o = lse_sh[lrow];
                    float M = fmaxf(msm[mb][half], o.x);
                    float S = mss[mb][half] * expf(msm[mb][half] - M) +
                              o.y * expf(o.x - M);
                    lse[(long)(row0 + lrow) * gridDim.y + blockIdx.y] = make_float2(M, S);
                }
            }
        }
    }
}

// ---------------- transpose + fp32->fp16 -------------------------------------
__global__ void transpose_half(const float* __restrict__ src, __half* __restrict__ dst,
                               int R, int Ccols) {
    __shared__ float t[32][33];
    long ofs = (long)blockIdx.z * R * Ccols;
    src += ofs; dst += ofs;
    int bx = blockIdx.x * 32, by = blockIdx.y * 32;
    int x = bx + threadIdx.x;
    #pragma unroll
    for (int j = 0; j < 32; j += 8) {
        int y = by + threadIdx.y + j;
        t[threadIdx.y + j][threadIdx.x] = src[(long)y * Ccols + x];
    }
    __syncthreads();
    x = by + threadIdx.x;
    #pragma unroll
    for (int j = 0; j < 32; j += 8) {
        int y = bx + threadIdx.y + j;
        dst[(long)y * R + x] = __float2half_rn(t[threadIdx.x][threadIdx.y + j]);
    }
}

// ---------------- fp32 -> fp16 convert ---------------------------------------
__global__ void tohalf_kernel(const float* __restrict__ src, __half* __restrict__ dst,
                              long n4) {
    long i = (long)blockIdx.x * blockDim.x + threadIdx.x;
    long stride = (long)gridDim.x * blockDim.x;
    for (; i < n4; i += stride) {
        float4 v = ((const float4*)src)[i];
        ((__half2*)dst)[i * 2]     = __floats2half2_rn(v.x, v.y);
        ((__half2*)dst)[i * 2 + 1] = __floats2half2_rn(v.z, v.w);
    }
}

// ---------------- embedding gather ------------------------------------------
__global__ void embed_kernel(const int* __restrict__ x, const float* __restrict__ enc,
                             float* __restrict__ z) {
    int row = blockIdx.x;
    int tok = x[row];
    const float4* src = (const float4*)(enc + (long)tok * D_MODEL);
    float4* dst = (float4*)(z + (long)row * D_MODEL);
    for (int i = threadIdx.x; i < D_MODEL / 4; i += blockDim.x) dst[i] = src[i];
}

// ---------------- (buggy) LayerNorm, warp-per-row, fp32 input ----------------
__global__ __launch_bounds__(256) void ln_kernel(
    const float* __restrict__ in, const float* __restrict__ gamma,
    const float* __restrict__ beta, __half* __restrict__ outf) {
    int row  = blockIdx.x * 8 + (threadIdx.x >> 5);
    int lane = threadIdx.x & 31;
    const float4* xr = (const float4*)(in + (long)row * D_MODEL);

    float4 xv[8];
    float s = 0.f, s2 = 0.f;
    #pragma unroll
    for (int j = 0; j < 8; j++) {
        xv[j] = xr[lane + 32 * j];
        s  += xv[j].x + xv[j].y + xv[j].z + xv[j].w;
        s2 += xv[j].x * xv[j].x + xv[j].y * xv[j].y
            + xv[j].z * xv[j].z + xv[j].w * xv[j].w;
    }
    float S  = warp_red<0>(s);
    float S2 = warp_red<0>(s2);
    float mu  = S * (1.f / (float)D_MODEL);
    float var = (S2 - (float)D_MODEL * mu * mu) * (1.f / (float)(D_MODEL - 1));
    float shift = mu * rsqrtf(var);

    #pragma unroll
    for (int j = 0; j < 8; j++) {
        float4 g = ((const float4*)gamma)[lane + 32 * j];
        float4 b = ((const float4*)beta)[lane + 32 * j];
        long base = (long)row * D_MODEL + (lane + 32 * j) * 4;
        *(__half2*)(outf + base)     = __floats2half2_rn((xv[j].x - shift) * g.x + b.x,
                                                         (xv[j].y - shift) * g.y + b.y);
        *(__half2*)(outf + base + 2) = __floats2half2_rn((xv[j].z - shift) * g.z + b.z,
                                                         (xv[j].w - shift) * g.w + b.w);
    }
}

// ---------------- (buggy) LayerNorm, warp-per-row, fp16 input ----------------
__global__ __launch_bounds__(256) void ln_h_kernel(
    const __half* __restrict__ in, const float* __restrict__ gamma,
    const float* __restrict__ beta, __half* __restrict__ outf) {
    int row  = blockIdx.x * 8 + (threadIdx.x >> 5);
    int lane = threadIdx.x & 31;
    const uint4* xr = (const uint4*)(in + (long)row * D_MODEL);

    float f[32];
    float s = 0.f, s2 = 0.f;
    #pragma unroll
    for (int j = 0; j < 4; j++) {
        uint4 r = xr[lane + 32 * j];
        h2f(r.x, f[j*8+0], f[j*8+1]); h2f(r.y, f[j*8+2], f[j*8+3]);
        h2f(r.z, f[j*8+4], f[j*8+5]); h2f(r.w, f[j*8+6], f[j*8+7]);
        #pragma unroll
        for (int k = 0; k < 8; k++) { s += f[j*8+k]; s2 += f[j*8+k] * f[j*8+k]; }
    }
    float S  = warp_red<0>(s);
    float S2 = warp_red<0>(s2);
    float mu  = S * (1.f / (float)D_MODEL);
    float var = (S2 - (float)D_MODEL * mu * mu) * (1.f / (float)(D_MODEL - 1));
    float shift = mu * rsqrtf(var);

    #pragma unroll
    for (int j = 0; j < 4; j++) {
        long base = (long)row * D_MODEL + (lane + 32 * j) * 8;
        #pragma unroll
        for (int t = 0; t < 2; t++) {
            float4 g = ((const float4*)gamma)[(lane + 32 * j) * 2 + t];
            float4 b = ((const float4*)beta)[(lane + 32 * j) * 2 + t];
            int o = j * 8 + t * 4;
            *(__half2*)(outf + base + t * 4)     = __floats2half2_rn((f[o+0] - shift) * g.x + b.x,
                                                                     (f[o+1] - shift) * g.y + b.y);
            *(__half2*)(outf + base + t * 4 + 2) = __floats2half2_rn((f[o+2] - shift) * g.z + b.z,
                                                                     (f[o+3] - shift) * g.w + b.w);
        }
    }
}

// ---------------- softmax, warp-per-row, fp16 in/out --------------------------
__global__ __launch_bounds__(256) void softmax_kernel(
    const __half* __restrict__ s, __half* __restrict__ outf) {
    int row  = blockIdx.x * 8 + (threadIdx.x >> 5);
    int lane = threadIdx.x & 31;
    const uint4* r4 = (const uint4*)(s + (long)row * SEQ);

    float f[32];
    float m = -1e30f;
    #pragma unroll
    for (int j = 0; j < 4; j++) {
        uint4 r = r4[lane + 32 * j];
        h2f(r.x, f[j*8+0], f[j*8+1]); h2f(r.y, f[j*8+2], f[j*8+3]);
        h2f(r.z, f[j*8+4], f[j*8+5]); h2f(r.w, f[j*8+6], f[j*8+7]);
        #pragma unroll
        for (int k = 0; k < 8; k++) m = fmaxf(m, f[j*8+k]);
    }
    float mx = warp_red<1>(m);

    float sum = 0.f;
    #pragma unroll
    for (int j = 0; j < 32; j++) { f[j] = expf(f[j] - mx); sum += f[j]; }
    float inv = 1.f / warp_red<0>(sum);

    #pragma unroll
    for (int j = 0; j < 4; j++) {
        long base = (long)row * SEQ + (lane + 32 * j) * 8;
        #pragma unroll
        for (int t = 0; t < 4; t++)
            *(__half2*)(outf + base + t * 2) =
                __floats2half2_rn(f[j*8 + t*2] * inv, f[j*8 + t*2 + 1] * inv);
    }
}

// ---------------- final NLL from per-colblock LSE partials -------------------
__global__ void nll_final(const float2* __restrict__ lse,
                          const float* __restrict__ logits,
                          const int* __restrict__ y, float* __restrict__ nll) {
    int row = blockIdx.x;
    int tid = threadIdx.x;

    float m = -1e30f, s = 0.f;
    if (tid < LSE_NB) {
        float2 p = lse[(long)row * LSE_NB + tid];
        m = p.x; s = p.y;
    }

    int lane = tid & 31, wid = tid >> 5;
    #pragma unroll
    for (int o = 16; o; o >>= 1) {
        float m2 = __shfl_xor_sync(0xffffffffu, m, o);
        float s2 = __shfl_xor_sync(0xffffffffu, s, o);
        float M = fmaxf(m, m2);
        s = s * expf(m - M) + s2 * expf(m2 - M);
        m = M;
    }
    __shared__ float sm_[8], ss_[8];
    if (lane == 0) { sm_[wid] = m; ss_[wid] = s; }
    __syncthreads();
    if (tid == 0) {
        float M = sm_[0];
        #pragma unroll
        for (int i = 1; i < 8; i++) M = fmaxf(M, sm_[i]);
        float S = 0.f;
        #pragma unroll
        for (int i = 0; i < 8; i++) S += ss_[i] * expf(sm_[i] - M);
        nll[row] = (M + logf(S)) - logits[(long)row * D_VOCAB + y[row]];
    }
}

__global__ void loss_reduce_kernel(const float* __restrict__ nll, float* __restrict__ out,
                                   long ofs) {
    __shared__ float red[256];
    int tid = threadIdx.x;
    float s = 0.f;
    for (int i = tid; i < BT; i += 256) s += nll[i];
    red[tid] = s; __syncthreads();
    #pragma unroll
    for (int o = 128; o > 0; o >>= 1) { if (tid < o) red[tid] += red[tid + o]; __syncthreads(); }
    if (tid == 0) out[ofs] = red[0] / (float)BT;
}

// ---------------- driver -----------------------------------------------------
extern "C" void kernel_launch(void* const* d_in, const int* in_sizes, int n_in,
                              void* d_out, int out_size) {
    (void)in_sizes; (void)n_in;
    const int*   x   = (const int*)  d_in[0];
    const int*   y   = (const int*)  d_in[1];
    const float* enc = (const float*)d_in[2];
    const float* g1  = (const float*)d_in[3];
    const float* b1  = (const float*)d_in[4];
    const float* wq  = (const float*)d_in[5];
    const float* wk  = (const float*)d_in[6];
    const float* wv  = (const float*)d_in[7];
    const float* g2  = (const float*)d_in[8];
    const float* b2  = (const float*)d_in[9];
    const float* w1  = (const float*)d_in[10];
    const float* bb1 = (const float*)d_in[11];
    const float* w2  = (const float*)d_in[12];
    const float* bb2 = (const float*)d_in[13];
    float* out = (float*)d_out;

    float *z, *nll;
    float2* lse;
    __half *ylnf, *qkf, *s16, *sf, *o16, *vTf, *hf, *zf, *encf, *wtf;
    cudaGetSymbolAddress((void**)&z,   g_z);
    cudaGetSymbolAddress((void**)&nll, g_nll);
    cudaGetSymbolAddress((void**)&lse, g_lse);
    cudaGetSymbolAddress((void**)&ylnf, g_ylnf);
    cudaGetSymbolAddress((void**)&qkf, g_qkf);
    cudaGetSymbolAddress((void**)&s16, g_s16);
    cudaGetSymbolAddress((void**)&sf, g_sf);
    cudaGetSymbolAddress((void**)&o16, g_o16);
    cudaGetSymbolAddress((void**)&vTf, g_vTf);
    cudaGetSymbolAddress((void**)&hf, g_hf);
    cudaGetSymbolAddress((void**)&zf, g_zf);
    cudaGetSymbolAddress((void**)&encf, g_encf);
    cudaGetSymbolAddress((void**)&wtf, g_wtf);

    static int inited = 0;
    static cudaStream_t sB = 0, sE = 0;
    static cudaEvent_t evRoot = 0, evB = 0, evEnc = 0;
    if (!inited) {
        cudaFuncSetAttribute(gemm_h, cudaFuncAttributeMaxDynamicSharedMemorySize,
                             NSTAGE * H_STAGE);
        cudaStreamCreateWithFlags(&sB, cudaStreamNonBlocking);
        cudaStreamCreateWithFlags(&sE, cudaStreamNonBlocking);
        cudaEventCreateWithFlags(&evRoot, cudaEventDisableTiming);
        cudaEventCreateWithFlags(&evB,    cudaEventDisableTiming);
        cudaEventCreateWithFlags(&evEnc,  cudaEventDisableTiming);
        inited = 1;
    }
    const int GH = NSTAGE * H_STAGE;

    const long DD = (long)D_MODEL * D_MODEL;
    const long SD = (long)SEQ * D_MODEL;
    const long SS = (long)SEQ * SEQ;
    const long S2L = (long)SEQ * D2;
    __half* wvTf = wtf + 2 * DD;
    __half* w1Tf = wtf + 3 * DD;
    __half* w2Tf = wtf + 4 * DD;

    dim3 tgrid(D_MODEL / 32, D_MODEL / 32, 1);
    dim3 tblk(32, 8);

    embed_kernel<<<BT, 256>>>(x, enc, z);
    transpose_half<<<tgrid, tblk>>>(wq, wtf + 0 * DD, D_MODEL, D_MODEL);
    transpose_half<<<tgrid, tblk>>>(wk, wtf + 1 * DD, D_MODEL, D_MODEL);
    transpose_half<<<tgrid, tblk>>>(wv, wvTf, D_MODEL, D_MODEL);
    transpose_half<<<tgrid, tblk>>>(w1, w1Tf, D_MODEL, D_MODEL);
    transpose_half<<<tgrid, tblk>>>(w2, w2Tf, D_MODEL, D_MODEL);

    // fork: both side streams start after the preamble
    cudaEventRecord(evRoot, 0);
    cudaStreamWaitEvent(sB, evRoot, 0);
    cudaStreamWaitEvent(sE, evRoot, 0);
    tohalf_kernel<<<1024, 256, 0, sE>>>(enc, encf, (long)D_VOCAB * D_MODEL / 4);
    cudaEventRecord(evEnc, sE);

    // per-half layer chain: batches [b0, b0+2) fully sequential on stream st
    const int HB = 2;                       // batches per half
    const int HR = HB * SEQ;                // 2048 rows per half
    dim3 grid_qk_h (HR / 128, D2 / 128);          // (16, 16)
    dim3 grid_proj_h(HR / 128, D_MODEL / 128);    // (16, 8)
    dim3 grid_attn_h(SEQ / 128, SEQ / 128, HB);   // (8, 8, 2)
    dim3 grid_vT_h (D_MODEL / 128, SEQ / 128, HB);// (8, 8, 2)

    auto half_chain = [&](cudaStream_t st, int b0, int layer) {
        long R0D = (long)b0 * SEQ * D_MODEL;
        long R0Q = (long)b0 * SEQ * D2;
        long R0S = (long)b0 * SS;

        ln_kernel<<<HR / 8, 256, 0, st>>>(z + R0D, g1, b1, ylnf + R0D);

        gemm_h<<<grid_qk_h, 256, GH, st>>>(ylnf + R0D, wtf, nullptr, nullptr, qkf + R0Q,
                                           D_MODEL, D_MODEL, D2, 0, 0, 0, D_MODEL, 1.f, 8);

        gemm_h<<<grid_vT_h, 256, GH, st>>>(wvTf, ylnf + R0D, nullptr, nullptr, vTf + R0D,
                                           D_MODEL, D_MODEL, SEQ, 0, SD, SD, D_MODEL, 1.f, 8);

        gemm_h<<<grid_attn_h, 256, GH, st>>>(qkf + R0Q, qkf + R0Q + D_MODEL,
                                             nullptr, nullptr, s16 + R0S,
                                             D2, D2, SEQ, S2L, S2L, SS, D_MODEL,
                                             0.03125f, 8);

        softmax_kernel<<<HB * SEQ / 8, 256, 0, st>>>(s16 + R0S, sf + R0S);

        gemm_h<<<grid_attn_h, 256, GH, st>>>(sf + R0S, vTf + R0D, nullptr, nullptr, o16 + R0D,
                                             SEQ, SEQ, D_MODEL, SS, SD, SD, SEQ, 1.f, 8);

        ln_h_kernel<<<HR / 8, 256, 0, st>>>(o16 + R0D, g2, b2, ylnf + R0D);

        gemm_h<<<grid_proj_h, 256, GH, st>>>(ylnf + R0D, w1Tf, bb1, nullptr, hf + R0D,
                                             D_MODEL, D_MODEL, D_MODEL, 0, 0, 0, D_MODEL,
                                             1.f, 8 | 4 | 1);
        int w2flags = 16 | 4 | 2 | ((layer == NLAYERS - 1) ? 8 : 0);
        gemm_h<<<grid_proj_h, 256, GH, st>>>(hf + R0D, w2Tf, bb2, z + R0D,
                                             (layer == NLAYERS - 1) ? zf + R0D : nullptr,
                                             D_MODEL, D_MODEL, D_MODEL, 0, 0, 0, D_MODEL,
                                             1.f, w2flags);
    };

    for (int layer = 0; layer < NLAYERS; layer++) {
        half_chain(0,  0, layer);     // batches 0-1 on main stream
        half_chain(sB, 2, layer);     // batches 2-3 on side stream
    }
    cudaEventRecord(evB, sB);
    cudaStreamWaitEvent(0, evB, 0);
    cudaStreamWaitEvent(0, evEnc, 0);

    // logits = Z enc^T -> fp32, with fused per-colblock logsumexp partials
    dim3 grid_logits(BT / 128, D_VOCAB / 128);     // (32, 250)
    gemm_h<<<grid_logits, 256, GH>>>(zf, encf, nullptr, out, nullptr,
                                     D_MODEL, D_MODEL, D_VOCAB, 0, 0, 0, D_MODEL,
                                     1.f, 16 | 32);

    nll_final<<<BT, 256>>>(lse, out, y, nll);
    if ((long)out_size > BTV)
        loss_reduce_kernel<<<1, 256>>>(nll, out, BTV);
}